// round 1
// baseline (speedup 1.0000x reference)
#include <cuda_runtime.h>
#include <math.h>

#define D_MODEL 1024
#define NH 16
#define HD 64
#define BSZ 2
#define SEQL 2048
#define MTOT (BSZ*SEQL)

// scratch (allocation-free)
__device__ float g_q[(size_t)BSZ*NH*SEQL*HD];
__device__ float g_k[(size_t)BSZ*NH*SEQL*HD];
__device__ float g_v[(size_t)BSZ*NH*SEQL*HD];
__device__ float g_attn[(size_t)MTOT*D_MODEL];

// ---------------------------------------------------------------------------
// GEMM: Y[m,n] = sum_k A[m,k] * W[n,k]   (A: 4096x1024, W: 1024x1024, row-major)
// mode 0: plain write to out[m*1024+n]
// mode 1: RoPE + scatter to [b][h][s][d]
// mode 2: scatter (no rope)
// ---------------------------------------------------------------------------
#define BM 128
#define BN 128
#define BKD 16
#define LPAD 4

__global__ __launch_bounds__(256, 2)
void gemm_kernel(const float* __restrict__ A, const float* __restrict__ W,
                 float* __restrict__ out, int mode, const int* __restrict__ tokpos)
{
    __shared__ float As[BKD][BM + LPAD];
    __shared__ float Bs[BKD][BN + LPAD];
    const int m0 = blockIdx.y * BM;
    const int n0 = blockIdx.x * BN;
    const int tid = (int)threadIdx.x;
    const int ty = tid >> 4;
    const int tx = tid & 15;

    float acc[8][8];
#pragma unroll
    for (int i = 0; i < 8; ++i)
#pragma unroll
        for (int j = 0; j < 8; ++j) acc[i][j] = 0.f;

    for (int k0 = 0; k0 < D_MODEL; k0 += BKD) {
#pragma unroll
        for (int i = 0; i < 2; ++i) {
            int lin = tid + i * 256;
            int row = lin >> 2;
            int kc = (lin & 3) << 2;
            float4 va = *(const float4*)(A + (size_t)(m0 + row) * D_MODEL + k0 + kc);
            As[kc + 0][row] = va.x; As[kc + 1][row] = va.y;
            As[kc + 2][row] = va.z; As[kc + 3][row] = va.w;
            float4 vb = *(const float4*)(W + (size_t)(n0 + row) * D_MODEL + k0 + kc);
            Bs[kc + 0][row] = vb.x; Bs[kc + 1][row] = vb.y;
            Bs[kc + 2][row] = vb.z; Bs[kc + 3][row] = vb.w;
        }
        __syncthreads();
#pragma unroll
        for (int k = 0; k < BKD; ++k) {
            float a[8], bb[8];
            float4 t;
            t = *(const float4*)&As[k][ty * 4];      a[0]=t.x; a[1]=t.y; a[2]=t.z; a[3]=t.w;
            t = *(const float4*)&As[k][64 + ty * 4]; a[4]=t.x; a[5]=t.y; a[6]=t.z; a[7]=t.w;
            t = *(const float4*)&Bs[k][tx * 4];      bb[0]=t.x; bb[1]=t.y; bb[2]=t.z; bb[3]=t.w;
            t = *(const float4*)&Bs[k][64 + tx * 4]; bb[4]=t.x; bb[5]=t.y; bb[6]=t.z; bb[7]=t.w;
#pragma unroll
            for (int i = 0; i < 8; ++i)
#pragma unroll
                for (int j = 0; j < 8; ++j)
                    acc[i][j] = fmaf(a[i], bb[j], acc[i][j]);
        }
        __syncthreads();
    }

    int rows[8], cols[8];
#pragma unroll
    for (int i = 0; i < 4; ++i) { rows[i] = m0 + ty * 4 + i; rows[i + 4] = m0 + 64 + ty * 4 + i; }
#pragma unroll
    for (int j = 0; j < 4; ++j) { cols[j] = n0 + tx * 4 + j; cols[j + 4] = n0 + 64 + tx * 4 + j; }

    if (mode == 0) {
#pragma unroll
        for (int i = 0; i < 8; ++i)
#pragma unroll
            for (int j = 0; j < 8; ++j)
                out[(size_t)rows[i] * D_MODEL + cols[j]] = acc[i][j];
    } else {
#pragma unroll
        for (int i = 0; i < 8; ++i) {
            int m = rows[i];
            int b  = m >> 11;           // /SEQL
            int s  = m & (SEQL - 1);
            float pos = (float)tokpos[s];
#pragma unroll
            for (int jp = 0; jp < 8; jp += 2) {
                int n = cols[jp];
                int h = n >> 6;
                int d = n & 63;         // even
                size_t dst = ((size_t)(b * NH + h) * SEQL + s) * HD + d;
                float e = acc[i][jp], o = acc[i][jp + 1];
                if (mode == 1) {
                    // theta^(-d/64) = 2^(-d/64 * log2(10000))
                    float fr = exp2f((float)d * (-13.287712379549449f / 64.f));
                    float ang = pos * fr;
                    float cs, sn;
                    sincosf(ang, &sn, &cs);
                    out[dst]     = e * cs - o * sn;
                    out[dst + 1] = e * sn + o * cs;
                } else {
                    out[dst]     = e;
                    out[dst + 1] = o;
                }
            }
        }
    }
}

// ---------------------------------------------------------------------------
// Flash attention: one CTA per (b,h, q-tile of 64). 256 threads.
// thread -> (row r = tid/4, quad c4 = tid%3..): computes score cols 4j+c4 and
// output dims c4*16+j. Online softmax. Causal: kt <= qt.
// ---------------------------------------------------------------------------
#define QT 64
#define KT 64
#define SSTR 65

__global__ __launch_bounds__(256)
void flash_kernel(float* __restrict__ attnout)
{
    extern __shared__ float sm[];
    float* sQ = sm;
    float* sK = sQ + QT * SSTR;
    float* sV = sK + KT * SSTR;
    float* sP = sV + KT * SSTR;

    const int qt = (int)blockIdx.x;
    const int bh = (int)blockIdx.y;
    const int b  = bh >> 4;
    const int h  = bh & 15;
    const int tid = (int)threadIdx.x;

    const float* Qp = g_q + (size_t)bh * SEQL * HD;
    const float* Kp = g_k + (size_t)bh * SEQL * HD;
    const float* Vp = g_v + (size_t)bh * SEQL * HD;

    // load Q tile (scale folded in)
#pragma unroll
    for (int i = 0; i < 4; ++i) {
        int lin = tid + i * 256;        // float4 index, 1024 total
        int row = lin >> 4;
        int c = (lin & 15) << 2;
        float4 v = *(const float4*)(Qp + (size_t)(qt * QT + row) * HD + c);
        sQ[row * SSTR + c + 0] = v.x * 0.125f;
        sQ[row * SSTR + c + 1] = v.y * 0.125f;
        sQ[row * SSTR + c + 2] = v.z * 0.125f;
        sQ[row * SSTR + c + 3] = v.w * 0.125f;
    }

    const int r  = tid >> 2;
    const int c4 = tid & 3;
    const int od0 = c4 * 16;
    const int qidx = qt * QT + r;

    float mi = -1e30f, li = 0.f;
    float o[16];
#pragma unroll
    for (int j = 0; j < 16; ++j) o[j] = 0.f;

    for (int kt = 0; kt <= qt; ++kt) {
        __syncthreads();   // prev P@V done (and first-iter sQ visible)
#pragma unroll
        for (int i = 0; i < 4; ++i) {
            int lin = tid + i * 256;
            int row = lin >> 4;
            int c = (lin & 15) << 2;
            float4 v = *(const float4*)(Kp + (size_t)(kt * KT + row) * HD + c);
            sK[row * SSTR + c + 0] = v.x;
            sK[row * SSTR + c + 1] = v.y;
            sK[row * SSTR + c + 2] = v.z;
            sK[row * SSTR + c + 3] = v.w;
            float4 w = *(const float4*)(Vp + (size_t)(kt * KT + row) * HD + c);
            sV[row * SSTR + c + 0] = w.x;
            sV[row * SSTR + c + 1] = w.y;
            sV[row * SSTR + c + 2] = w.z;
            sV[row * SSTR + c + 3] = w.w;
        }
        __syncthreads();

        // scores: row r, cols 4j+c4
        float sc[16];
#pragma unroll
        for (int j = 0; j < 16; ++j) sc[j] = 0.f;
#pragma unroll 4
        for (int d = 0; d < HD; ++d) {
            float qv = sQ[r * SSTR + d];
#pragma unroll
            for (int j = 0; j < 16; ++j)
                sc[j] = fmaf(qv, sK[(j * 4 + c4) * SSTR + d], sc[j]);
        }
        if (kt == qt) {
#pragma unroll
            for (int j = 0; j < 16; ++j) {
                int kidx = kt * KT + j * 4 + c4;
                if (kidx > qidx) sc[j] = -1e30f;
            }
        }

        float mx = sc[0];
#pragma unroll
        for (int j = 1; j < 16; ++j) mx = fmaxf(mx, sc[j]);
        mx = fmaxf(mx, __shfl_xor_sync(0xffffffffu, mx, 1));
        mx = fmaxf(mx, __shfl_xor_sync(0xffffffffu, mx, 2));
        float mnew = fmaxf(mi, mx);
        float alpha = __expf(mi - mnew);

        float ps = 0.f;
#pragma unroll
        for (int j = 0; j < 16; ++j) {
            float p = __expf(sc[j] - mnew);
            sP[r * SSTR + j * 4 + c4] = p;
            ps += p;
        }
        ps += __shfl_xor_sync(0xffffffffu, ps, 1);
        ps += __shfl_xor_sync(0xffffffffu, ps, 2);
        li = li * alpha + ps;
        mi = mnew;
#pragma unroll
        for (int j = 0; j < 16; ++j) o[j] *= alpha;

        __syncwarp();      // sP row r written by this warp's 4-thread group

#pragma unroll 4
        for (int k = 0; k < KT; ++k) {
            float pv = sP[r * SSTR + k];
#pragma unroll
            for (int j = 0; j < 16; ++j)
                o[j] = fmaf(pv, sV[k * SSTR + od0 + j], o[j]);
        }
    }

    float inv = 1.f / li;
    float* dst = attnout + ((size_t)(b * SEQL) + qt * QT + r) * D_MODEL + h * HD + od0;
#pragma unroll
    for (int j = 0; j < 16; ++j) dst[j] = o[j] * inv;
}

// ---------------------------------------------------------------------------
extern "C" void kernel_launch(void* const* d_in, const int* in_sizes, int n_in,
                              void* d_out, int out_size)
{
    const float* x  = (const float*)d_in[0];
    const int*   tp = (const int*)d_in[1];
    const float* Wq = (const float*)d_in[2];
    const float* Wk = (const float*)d_in[3];
    const float* Wv = (const float*)d_in[4];
    const float* Wo = (const float*)d_in[5];
    float* out = (float*)d_out;

    float *qp, *kp, *vp, *ap;
    cudaGetSymbolAddress((void**)&qp, g_q);
    cudaGetSymbolAddress((void**)&kp, g_k);
    cudaGetSymbolAddress((void**)&vp, g_v);
    cudaGetSymbolAddress((void**)&ap, g_attn);

    const size_t flash_smem = (size_t)4 * QT * SSTR * sizeof(float);   // 66560 B
    cudaFuncSetAttribute(flash_kernel, cudaFuncAttributeMaxDynamicSharedMemorySize,
                         (int)flash_smem);

    dim3 gg(D_MODEL / BN, MTOT / BM);
    gemm_kernel<<<gg, 256>>>(x, Wq, qp, 1, tp);
    gemm_kernel<<<gg, 256>>>(x, Wk, kp, 1, tp);
    gemm_kernel<<<gg, 256>>>(x, Wv, vp, 2, tp);
    flash_kernel<<<dim3(SEQL / QT, BSZ * NH), 256, flash_smem>>>(ap);
    gemm_kernel<<<gg, 256>>>(ap, Wo, out, 0, tp);
}

// round 2
// speedup vs baseline: 1.8031x; 1.8031x over previous
#include <cuda_runtime.h>
#include <math.h>
#include <stdint.h>

#define D_MODEL 1024
#define NH 16
#define HD 64
#define BSZ 2
#define SEQL 2048
#define MTOT (BSZ*SEQL)

// scratch (allocation-free)
__device__ float g_q[(size_t)BSZ*NH*SEQL*HD];
__device__ float g_k[(size_t)BSZ*NH*SEQL*HD];
__device__ float g_v[(size_t)BSZ*NH*SEQL*HD];
__device__ float g_attn[(size_t)MTOT*D_MODEL];

__device__ __forceinline__ uint32_t f2tf32(float x) {
    uint32_t r;
    asm("cvt.rna.tf32.f32 %0, %1;" : "=r"(r) : "f"(x));
    return r;
}

__device__ __forceinline__ void mma_tf32(float* c, uint32_t a0, uint32_t a1,
                                         uint32_t a2, uint32_t a3,
                                         uint32_t b0, uint32_t b1) {
    asm volatile(
        "mma.sync.aligned.m16n8k8.row.col.f32.tf32.tf32.f32 "
        "{%0,%1,%2,%3}, {%4,%5,%6,%7}, {%8,%9}, {%0,%1,%2,%3};"
        : "+f"(c[0]), "+f"(c[1]), "+f"(c[2]), "+f"(c[3])
        : "r"(a0), "r"(a1), "r"(a2), "r"(a3), "r"(b0), "r"(b1));
}

__device__ __forceinline__ void cpa16(uint32_t dst, const void* src) {
    asm volatile("cp.async.cg.shared.global [%0], [%1], 16;" :: "r"(dst), "l"(src));
}
__device__ __forceinline__ void cpa_commit() {
    asm volatile("cp.async.commit_group;");
}
__device__ __forceinline__ void cpa_wait1() {
    asm volatile("cp.async.wait_group 1;");
}

// ---------------------------------------------------------------------------
// tf32 GEMM: Y[m,n] = sum_k A[m,k] * W[n,k]
// 128x128 tile, BK=32, 256 threads, warp tile 64x32 (4x4 m16n8k8 mmas/slice)
// mode 0: plain  ; mode 1: RoPE + scatter to [b][h][s][d] ; mode 2: scatter
// ---------------------------------------------------------------------------
#define GSTR 36          // smem row stride (floats) for BK=32 tile
#define GSTAGE 4608      // floats per A (or B) buffer: 128*36
#define GEMM_SMEM (2*2*GSTAGE*4)

__global__ __launch_bounds__(256)
void gemm_tf32(const float* __restrict__ A, const float* __restrict__ W,
               float* __restrict__ out, int mode, const int* __restrict__ tokpos)
{
    extern __shared__ float sm[];
    const int tid = (int)threadIdx.x;
    const int m0 = blockIdx.y * 128, n0 = blockIdx.x * 128;
    const int lane = tid & 31, wid = tid >> 5;
    const int g = lane >> 2, t = lane & 3;
    const int wm = (wid >> 2) * 64, wn = (wid & 3) * 32;

    const int c4 = (tid & 7) * 4;      // float column within BK tile
    const int r0 = tid >> 3;           // base row for loads
    uint32_t sbase = (uint32_t)__cvta_generic_to_shared(sm);

    float c[4][4][4];
#pragma unroll
    for (int i = 0; i < 4; ++i)
#pragma unroll
        for (int j = 0; j < 4; ++j)
#pragma unroll
            for (int k = 0; k < 4; ++k) c[i][j][k] = 0.f;

    // issue one stage of cp.async loads (A and B tiles)
#define ISSUE(stage, k0)                                                         \
    {                                                                            \
        uint32_t as_ = sbase + (uint32_t)(stage) * (2 * GSTAGE * 4);             \
        uint32_t bs_ = as_ + GSTAGE * 4;                                         \
        _Pragma("unroll")                                                        \
        for (int i_ = 0; i_ < 4; ++i_) {                                         \
            int row_ = r0 + 32 * i_;                                             \
            cpa16(as_ + (uint32_t)(row_ * GSTR + c4) * 4,                        \
                  A + (size_t)(m0 + row_) * D_MODEL + (k0) + c4);                \
            cpa16(bs_ + (uint32_t)(row_ * GSTR + c4) * 4,                        \
                  W + (size_t)(n0 + row_) * D_MODEL + (k0) + c4);                \
        }                                                                        \
        cpa_commit();                                                            \
    }

    ISSUE(0, 0);
    ISSUE(1, 32);

    for (int kt = 0; kt < 32; ++kt) {
        cpa_wait1();
        __syncthreads();
        const float* As = sm + (kt & 1) * (2 * GSTAGE);
        const float* Bs = As + GSTAGE;

#pragma unroll
        for (int ks = 0; ks < 4; ++ks) {
            uint32_t af[4][4], bf[4][2];
#pragma unroll
            for (int mt = 0; mt < 4; ++mt) {
                const float* p = As + (wm + mt * 16 + g) * GSTR + ks * 8 + t;
                af[mt][0] = f2tf32(p[0]);
                af[mt][1] = f2tf32(p[8 * GSTR]);
                af[mt][2] = f2tf32(p[4]);
                af[mt][3] = f2tf32(p[8 * GSTR + 4]);
            }
#pragma unroll
            for (int nt = 0; nt < 4; ++nt) {
                const float* p = Bs + (wn + nt * 8 + g) * GSTR + ks * 8 + t;
                bf[nt][0] = f2tf32(p[0]);
                bf[nt][1] = f2tf32(p[4]);
            }
#pragma unroll
            for (int mt = 0; mt < 4; ++mt)
#pragma unroll
                for (int nt = 0; nt < 4; ++nt)
                    mma_tf32(c[mt][nt], af[mt][0], af[mt][1], af[mt][2], af[mt][3],
                             bf[nt][0], bf[nt][1]);
        }
        __syncthreads();
        if (kt + 2 < 32) { ISSUE(kt & 1, (kt + 2) * 32); }
        else             { cpa_commit(); }
    }

    // epilogue
    if (mode == 0) {
#pragma unroll
        for (int mt = 0; mt < 4; ++mt) {
            int rowa = m0 + wm + mt * 16 + g;
#pragma unroll
            for (int nt = 0; nt < 4; ++nt) {
                int col = n0 + wn + nt * 8 + 2 * t;
                *(float2*)(out + (size_t)rowa * D_MODEL + col) =
                    make_float2(c[mt][nt][0], c[mt][nt][1]);
                *(float2*)(out + (size_t)(rowa + 8) * D_MODEL + col) =
                    make_float2(c[mt][nt][2], c[mt][nt][3]);
            }
        }
    } else {
#pragma unroll
        for (int mt = 0; mt < 4; ++mt) {
#pragma unroll
            for (int half = 0; half < 2; ++half) {
                int m = m0 + wm + mt * 16 + g + half * 8;
                int b = m >> 11;
                int s = m & (SEQL - 1);
                float pos = (float)tokpos[s];
#pragma unroll
                for (int nt = 0; nt < 4; ++nt) {
                    int col = n0 + wn + nt * 8 + 2 * t;   // even
                    int h = col >> 6;
                    int d = col & 63;
                    float e = c[mt][nt][half * 2 + 0];
                    float o = c[mt][nt][half * 2 + 1];
                    size_t dst = ((size_t)(b * NH + h) * SEQL + s) * HD + d;
                    if (mode == 1) {
                        float fr = exp2f((float)d * (-13.287712379549449f / 64.f));
                        float cs, sn;
                        sincosf(pos * fr, &sn, &cs);
                        *(float2*)(out + dst) = make_float2(e * cs - o * sn,
                                                            e * sn + o * cs);
                    } else {
                        *(float2*)(out + dst) = make_float2(e, o);
                    }
                }
            }
        }
    }
}

// ---------------------------------------------------------------------------
// Flash attention (fp32, float4-vectorized smem). One CTA per (b,h,qtile=64).
// thread: row r = tid>>2, quad c4 = tid&3. Score cols 4j+c4.
// Output cols owned: 4*c4 + 16*j4 + {0..3}.
// ---------------------------------------------------------------------------
#define QT 64
#define KT 64
#define SSTR 68          // floats per row (16B aligned, conflict-free)
#define FLASH_SMEM (4 * QT * SSTR * 4)

__global__ __launch_bounds__(256)
void flash_kernel(float* __restrict__ attnout)
{
    extern __shared__ float sm[];
    float* sQ = sm;
    float* sK = sQ + QT * SSTR;
    float* sV = sK + KT * SSTR;
    float* sP = sV + KT * SSTR;
    float4* sQ4 = (float4*)sQ;
    float4* sK4 = (float4*)sK;
    float4* sV4 = (float4*)sV;
    float4* sP4 = (float4*)sP;

    const int qt = (int)blockIdx.x;
    const int bh = (int)blockIdx.y;
    const int b  = bh >> 4;
    const int h  = bh & 15;
    const int tid = (int)threadIdx.x;

    const float* Qp = g_q + (size_t)bh * SEQL * HD;
    const float* Kp = g_k + (size_t)bh * SEQL * HD;
    const float* Vp = g_v + (size_t)bh * SEQL * HD;

#pragma unroll
    for (int i = 0; i < 4; ++i) {
        int lin = tid + i * 256;
        int row = lin >> 4;
        int cc = lin & 15;
        float4 v = *(const float4*)(Qp + (size_t)(qt * QT + row) * HD + cc * 4);
        v.x *= 0.125f; v.y *= 0.125f; v.z *= 0.125f; v.w *= 0.125f;
        sQ4[row * (SSTR / 4) + cc] = v;
    }

    const int r  = tid >> 2;
    const int c4 = tid & 3;
    const int qidx = qt * QT + r;

    float mi = -1e30f, li = 0.f;
    float4 o4[4];
#pragma unroll
    for (int j = 0; j < 4; ++j) o4[j] = make_float4(0.f, 0.f, 0.f, 0.f);

    for (int kt = 0; kt <= qt; ++kt) {
        __syncthreads();
#pragma unroll
        for (int i = 0; i < 4; ++i) {
            int lin = tid + i * 256;
            int row = lin >> 4;
            int cc = lin & 15;
            sK4[row * (SSTR / 4) + cc] =
                *(const float4*)(Kp + (size_t)(kt * KT + row) * HD + cc * 4);
            sV4[row * (SSTR / 4) + cc] =
                *(const float4*)(Vp + (size_t)(kt * KT + row) * HD + cc * 4);
        }
        __syncthreads();

        float sc[16];
#pragma unroll
        for (int j = 0; j < 16; ++j) sc[j] = 0.f;
#pragma unroll 4
        for (int dc = 0; dc < 16; ++dc) {
            float4 qv = sQ4[r * (SSTR / 4) + dc];
#pragma unroll
            for (int j = 0; j < 16; ++j) {
                float4 kv = sK4[(j * 4 + c4) * (SSTR / 4) + dc];
                sc[j] = fmaf(qv.x, kv.x, sc[j]);
                sc[j] = fmaf(qv.y, kv.y, sc[j]);
                sc[j] = fmaf(qv.z, kv.z, sc[j]);
                sc[j] = fmaf(qv.w, kv.w, sc[j]);
            }
        }
        if (kt == qt) {
#pragma unroll
            for (int j = 0; j < 16; ++j)
                if (kt * KT + j * 4 + c4 > qidx) sc[j] = -1e30f;
        }

        float mx = sc[0];
#pragma unroll
        for (int j = 1; j < 16; ++j) mx = fmaxf(mx, sc[j]);
        mx = fmaxf(mx, __shfl_xor_sync(0xffffffffu, mx, 1));
        mx = fmaxf(mx, __shfl_xor_sync(0xffffffffu, mx, 2));
        float mnew = fmaxf(mi, mx);
        float alpha = __expf(mi - mnew);

        float ps = 0.f;
#pragma unroll
        for (int j = 0; j < 16; ++j) {
            float p = __expf(sc[j] - mnew);
            sP[r * SSTR + j * 4 + c4] = p;
            ps += p;
        }
        ps += __shfl_xor_sync(0xffffffffu, ps, 1);
        ps += __shfl_xor_sync(0xffffffffu, ps, 2);
        li = li * alpha + ps;
        mi = mnew;
#pragma unroll
        for (int j = 0; j < 4; ++j) {
            o4[j].x *= alpha; o4[j].y *= alpha; o4[j].z *= alpha; o4[j].w *= alpha;
        }

        __syncwarp();

#pragma unroll 4
        for (int k4 = 0; k4 < 16; ++k4) {
            float4 p = sP4[r * (SSTR / 4) + k4];
            float pe[4] = {p.x, p.y, p.z, p.w};
#pragma unroll
            for (int e = 0; e < 4; ++e) {
                float pv = pe[e];
                int krow = k4 * 4 + e;
#pragma unroll
                for (int j4 = 0; j4 < 4; ++j4) {
                    float4 v = sV4[krow * (SSTR / 4) + c4 + 4 * j4];
                    o4[j4].x = fmaf(pv, v.x, o4[j4].x);
                    o4[j4].y = fmaf(pv, v.y, o4[j4].y);
                    o4[j4].z = fmaf(pv, v.z, o4[j4].z);
                    o4[j4].w = fmaf(pv, v.w, o4[j4].w);
                }
            }
        }
    }

    float inv = 1.f / li;
    float* dst = attnout + ((size_t)(b * SEQL) + qt * QT + r) * D_MODEL
               + h * HD + c4 * 4;
#pragma unroll
    for (int j4 = 0; j4 < 4; ++j4) {
        float4 v = o4[j4];
        v.x *= inv; v.y *= inv; v.z *= inv; v.w *= inv;
        *(float4*)(dst + 16 * j4) = v;
    }
}

// ---------------------------------------------------------------------------
extern "C" void kernel_launch(void* const* d_in, const int* in_sizes, int n_in,
                              void* d_out, int out_size)
{
    const float* x  = (const float*)d_in[0];
    const int*   tp = (const int*)d_in[1];
    const float* Wq = (const float*)d_in[2];
    const float* Wk = (const float*)d_in[3];
    const float* Wv = (const float*)d_in[4];
    const float* Wo = (const float*)d_in[5];
    float* out = (float*)d_out;

    float *qp, *kp, *vp, *ap;
    cudaGetSymbolAddress((void**)&qp, g_q);
    cudaGetSymbolAddress((void**)&kp, g_k);
    cudaGetSymbolAddress((void**)&vp, g_v);
    cudaGetSymbolAddress((void**)&ap, g_attn);

    static int inited = 0;
    if (!inited) {
        cudaFuncSetAttribute(gemm_tf32, cudaFuncAttributeMaxDynamicSharedMemorySize,
                             GEMM_SMEM);
        cudaFuncSetAttribute(flash_kernel, cudaFuncAttributeMaxDynamicSharedMemorySize,
                             FLASH_SMEM);
        inited = 1;
    }

    dim3 gg(D_MODEL / 128, MTOT / 128);
    gemm_tf32<<<gg, 256, GEMM_SMEM>>>(x, Wq, qp, 1, tp);
    gemm_tf32<<<gg, 256, GEMM_SMEM>>>(x, Wk, kp, 1, tp);
    gemm_tf32<<<gg, 256, GEMM_SMEM>>>(x, Wv, vp, 2, tp);
    flash_kernel<<<dim3(SEQL / QT, BSZ * NH), 256, FLASH_SMEM>>>(ap);
    gemm_tf32<<<gg, 256, GEMM_SMEM>>>(ap, Wo, out, 0, tp);
}

// round 3
// speedup vs baseline: 5.7215x; 3.1732x over previous
#include <cuda_runtime.h>
#include <math.h>
#include <stdint.h>

#define D_MODEL 1024
#define NH 16
#define HD 64
#define BSZ 2
#define SEQL 2048
#define MTOT (BSZ*SEQL)

// scratch (allocation-free) — all q/k/v/attn/xc/wc hold tf32-rounded fp32 bits
__device__ float g_q[(size_t)BSZ*NH*SEQL*HD];
__device__ float g_k[(size_t)BSZ*NH*SEQL*HD];
__device__ float g_v[(size_t)BSZ*NH*SEQL*HD];
__device__ float g_attn[(size_t)MTOT*D_MODEL];
__device__ float g_xc[(size_t)MTOT*D_MODEL];
__device__ float g_wc[4][(size_t)D_MODEL*D_MODEL];

// log2(e)/8 : folded into Q so softmax uses exp2
#define QSCALE 0.18033688011112042f

__device__ __forceinline__ uint32_t f2tf32(float x) {
    uint32_t r;
    asm("cvt.rna.tf32.f32 %0, %1;" : "=r"(r) : "f"(x));
    return r;
}

__device__ __forceinline__ void mma_tf32(float* c, uint32_t a0, uint32_t a1,
                                         uint32_t a2, uint32_t a3,
                                         uint32_t b0, uint32_t b1) {
    asm volatile(
        "mma.sync.aligned.m16n8k8.row.col.f32.tf32.tf32.f32 "
        "{%0,%1,%2,%3}, {%4,%5,%6,%7}, {%8,%9}, {%0,%1,%2,%3};"
        : "+f"(c[0]), "+f"(c[1]), "+f"(c[2]), "+f"(c[3])
        : "r"(a0), "r"(a1), "r"(a2), "r"(a3), "r"(b0), "r"(b1));
}

__device__ __forceinline__ void cpa16(uint32_t dst, const void* src) {
    asm volatile("cp.async.cg.shared.global [%0], [%1], 16;" :: "r"(dst), "l"(src));
}
__device__ __forceinline__ void cpa_commit() { asm volatile("cp.async.commit_group;"); }
__device__ __forceinline__ void cpa_wait1()  { asm volatile("cp.async.wait_group 1;"); }
__device__ __forceinline__ void cpa_wait0()  { asm volatile("cp.async.wait_group 0;"); }

// ---------------------------------------------------------------------------
// tf32 convert passes
// ---------------------------------------------------------------------------
__global__ void cvt1_kernel(const float4* __restrict__ src, float4* __restrict__ dst, int n4)
{
    int i = blockIdx.x * blockDim.x + threadIdx.x;
    if (i < n4) {
        float4 v = src[i];
        v.x = __uint_as_float(f2tf32(v.x));
        v.y = __uint_as_float(f2tf32(v.y));
        v.z = __uint_as_float(f2tf32(v.z));
        v.w = __uint_as_float(f2tf32(v.w));
        dst[i] = v;
    }
}

__global__ void cvt4_kernel(const float4* __restrict__ w0, const float4* __restrict__ w1,
                            const float4* __restrict__ w2, const float4* __restrict__ w3)
{
    int z = blockIdx.y;
    const float4* src = z == 0 ? w0 : z == 1 ? w1 : z == 2 ? w2 : w3;
    float4* dst = (float4*)g_wc[z];
    int i = blockIdx.x * blockDim.x + threadIdx.x;
    float4 v = src[i];
    v.x = __uint_as_float(f2tf32(v.x));
    v.y = __uint_as_float(f2tf32(v.y));
    v.z = __uint_as_float(f2tf32(v.z));
    v.w = __uint_as_float(f2tf32(v.w));
    dst[i] = v;
}

// ---------------------------------------------------------------------------
// tf32 GEMM: Y[m,n] = sum_k A[m,k] * W[n,k]  (A, W already tf32-rounded bits)
// 128x128 tile, BK=32, 256 threads, warp tile 64x32.
// mode 0: plain fp32 write; 1: RoPE*QSCALE + tf32 scatter (Q);
// 3: RoPE + tf32 scatter (K); 2: tf32 scatter (V)
// ---------------------------------------------------------------------------
#define GSTR 36
#define GSTAGE 4608
#define GEMM_SMEM (2*2*GSTAGE*4)

__global__ __launch_bounds__(256)
void gemm_tf32(const float* __restrict__ A,
               const float* __restrict__ W0, const float* __restrict__ W1,
               const float* __restrict__ W2,
               float* __restrict__ o0, float* __restrict__ o1, float* __restrict__ o2,
               int md0, int md1, int md2, const int* __restrict__ tokpos)
{
    extern __shared__ float sm[];
    const int z = blockIdx.z;
    const float* W = z == 0 ? W0 : z == 1 ? W1 : W2;
    float* out     = z == 0 ? o0 : z == 1 ? o1 : o2;
    const int mode = z == 0 ? md0 : z == 1 ? md1 : md2;

    const int tid = (int)threadIdx.x;
    const int m0 = blockIdx.y * 128, n0 = blockIdx.x * 128;
    const int lane = tid & 31, wid = tid >> 5;
    const int g = lane >> 2, t = lane & 3;
    const int wm = (wid >> 2) * 64, wn = (wid & 3) * 32;

    const int c4 = (tid & 7) * 4;
    const int r0 = tid >> 3;
    uint32_t sbase = (uint32_t)__cvta_generic_to_shared(sm);

    float c[4][4][4];
#pragma unroll
    for (int i = 0; i < 4; ++i)
#pragma unroll
        for (int j = 0; j < 4; ++j)
#pragma unroll
            for (int k = 0; k < 4; ++k) c[i][j][k] = 0.f;

#define ISSUE(stage, k0)                                                         \
    {                                                                            \
        uint32_t as_ = sbase + (uint32_t)(stage) * (2 * GSTAGE * 4);             \
        uint32_t bs_ = as_ + GSTAGE * 4;                                         \
        _Pragma("unroll")                                                        \
        for (int i_ = 0; i_ < 4; ++i_) {                                         \
            int row_ = r0 + 32 * i_;                                             \
            cpa16(as_ + (uint32_t)(row_ * GSTR + c4) * 4,                        \
                  A + (size_t)(m0 + row_) * D_MODEL + (k0) + c4);                \
            cpa16(bs_ + (uint32_t)(row_ * GSTR + c4) * 4,                        \
                  W + (size_t)(n0 + row_) * D_MODEL + (k0) + c4);                \
        }                                                                        \
        cpa_commit();                                                            \
    }

    ISSUE(0, 0);
    ISSUE(1, 32);

    for (int kt = 0; kt < 32; ++kt) {
        cpa_wait1();
        __syncthreads();
        const float* As = sm + (kt & 1) * (2 * GSTAGE);
        const float* Bs = As + GSTAGE;

#pragma unroll
        for (int ks = 0; ks < 4; ++ks) {
            uint32_t af[4][4], bf[4][2];
#pragma unroll
            for (int mt = 0; mt < 4; ++mt) {
                const float* p = As + (wm + mt * 16 + g) * GSTR + ks * 8 + t;
                af[mt][0] = __float_as_uint(p[0]);
                af[mt][1] = __float_as_uint(p[8 * GSTR]);
                af[mt][2] = __float_as_uint(p[4]);
                af[mt][3] = __float_as_uint(p[8 * GSTR + 4]);
            }
#pragma unroll
            for (int nt = 0; nt < 4; ++nt) {
                const float* p = Bs + (wn + nt * 8 + g) * GSTR + ks * 8 + t;
                bf[nt][0] = __float_as_uint(p[0]);
                bf[nt][1] = __float_as_uint(p[4]);
            }
#pragma unroll
            for (int mt = 0; mt < 4; ++mt)
#pragma unroll
                for (int nt = 0; nt < 4; ++nt)
                    mma_tf32(c[mt][nt], af[mt][0], af[mt][1], af[mt][2], af[mt][3],
                             bf[nt][0], bf[nt][1]);
        }
        __syncthreads();
        if (kt + 2 < 32) { ISSUE(kt & 1, (kt + 2) * 32); }
        else             { cpa_commit(); }
    }

    if (mode == 0) {
#pragma unroll
        for (int mt = 0; mt < 4; ++mt) {
            int rowa = m0 + wm + mt * 16 + g;
#pragma unroll
            for (int nt = 0; nt < 4; ++nt) {
                int col = n0 + wn + nt * 8 + 2 * t;
                *(float2*)(out + (size_t)rowa * D_MODEL + col) =
                    make_float2(c[mt][nt][0], c[mt][nt][1]);
                *(float2*)(out + (size_t)(rowa + 8) * D_MODEL + col) =
                    make_float2(c[mt][nt][2], c[mt][nt][3]);
            }
        }
    } else {
#pragma unroll
        for (int mt = 0; mt < 4; ++mt) {
#pragma unroll
            for (int half = 0; half < 2; ++half) {
                int m = m0 + wm + mt * 16 + g + half * 8;
                int b = m >> 11;
                int s = m & (SEQL - 1);
                float pos = (float)tokpos[s];
#pragma unroll
                for (int nt = 0; nt < 4; ++nt) {
                    int col = n0 + wn + nt * 8 + 2 * t;   // even
                    int h = col >> 6;
                    int d = col & 63;
                    float e = c[mt][nt][half * 2 + 0];
                    float o = c[mt][nt][half * 2 + 1];
                    size_t dst = ((size_t)(b * NH + h) * SEQL + s) * HD + d;
                    if (mode != 2) {
                        float fr = exp2f((float)d * (-13.287712379549449f / 64.f));
                        float cs, sn;
                        sincosf(pos * fr, &sn, &cs);
                        float re = e * cs - o * sn;
                        float ro = e * sn + o * cs;
                        if (mode == 1) { re *= QSCALE; ro *= QSCALE; }
                        *(float2*)(out + dst) = make_float2(
                            __uint_as_float(f2tf32(re)), __uint_as_float(f2tf32(ro)));
                    } else {
                        *(float2*)(out + dst) = make_float2(
                            __uint_as_float(f2tf32(e)), __uint_as_float(f2tf32(o)));
                    }
                }
            }
        }
    }
}

// ---------------------------------------------------------------------------
// Flash attention with tf32 mma. CTA: 128 threads (4 warps), QT=64, KT=64.
// Warp w owns q rows [16w,16w+16). Q frags in regs; K/V double-buffered via
// cp.async; P staged in smem for A-operand re-fragmentation.
// Q already holds tf32(rope(q) * log2e/8); probs via exp2.
// ---------------------------------------------------------------------------
#define FSTR 68
#define FLASH_SMEM (5 * 64 * FSTR * 4)   // sK[2] + sV[2] + sP

__device__ __forceinline__ void kv_issue(uint32_t sbase, int stage,
                                         const float* Kp, const float* Vp,
                                         int tile, int tid)
{
    uint32_t dK = sbase + (uint32_t)(stage * 64 * FSTR) * 4;
    uint32_t dV = sbase + (uint32_t)((2 + stage) * 64 * FSTR) * 4;
#pragma unroll
    for (int i = 0; i < 8; ++i) {
        int lin = tid + i * 128;
        int row = lin >> 4;
        int cc = (lin & 15) * 4;
        cpa16(dK + (uint32_t)(row * FSTR + cc) * 4,
              Kp + (size_t)(tile * 64 + row) * HD + cc);
        cpa16(dV + (uint32_t)(row * FSTR + cc) * 4,
              Vp + (size_t)(tile * 64 + row) * HD + cc);
    }
    cpa_commit();
}

__global__ __launch_bounds__(128)
void flash_mma(float* __restrict__ attnout)
{
    extern __shared__ float sm[];
    float* sP = sm + 4 * 64 * FSTR;
    uint32_t sbase = (uint32_t)__cvta_generic_to_shared(sm);

    const int qt = (int)blockIdx.x;
    const int bh = (int)blockIdx.y;
    const int b  = bh >> 4;
    const int h  = bh & 15;
    const int tid = (int)threadIdx.x;
    const int wid = tid >> 5, lane = tid & 31;
    const int g = lane >> 2, t = lane & 3;
    const int wm = wid * 16;

    const float* Qp = g_q + (size_t)bh * SEQL * HD;
    const float* Kp = g_k + (size_t)bh * SEQL * HD;
    const float* Vp = g_v + (size_t)bh * SEQL * HD;

    // stage Q tile in sP, pick up A-fragments into registers
#pragma unroll
    for (int i = 0; i < 8; ++i) {
        int lin = tid + i * 128;
        int row = lin >> 4;
        int cc = (lin & 15) * 4;
        *(float4*)&sP[row * FSTR + cc] =
            *(const float4*)(Qp + (size_t)(qt * 64 + row) * HD + cc);
    }
    __syncthreads();
    uint32_t aq[8][4];
#pragma unroll
    for (int ks = 0; ks < 8; ++ks) {
        const float* p = sP + (wm + g) * FSTR + ks * 8 + t;
        aq[ks][0] = __float_as_uint(p[0]);
        aq[ks][1] = __float_as_uint(p[8 * FSTR]);
        aq[ks][2] = __float_as_uint(p[4]);
        aq[ks][3] = __float_as_uint(p[8 * FSTR + 4]);
    }
    __syncthreads();

    float m0 = -1e30f, m1 = -1e30f, l0 = 0.f, l1 = 0.f;
    float o[8][4];
#pragma unroll
    for (int n = 0; n < 8; ++n)
#pragma unroll
        for (int e = 0; e < 4; ++e) o[n][e] = 0.f;

    kv_issue(sbase, 0, Kp, Vp, 0, tid);
    if (qt > 0) kv_issue(sbase, 1, Kp, Vp, 1, tid);

    for (int kt = 0; kt <= qt; ++kt) {
        const int cur = kt & 1;
        if (kt < qt) cpa_wait1(); else cpa_wait0();
        __syncthreads();
        const float* K0 = sm + cur * 64 * FSTR;
        const float* V0 = sm + (2 + cur) * 64 * FSTR;

        // S = Q @ K^T
        float cs[8][4];
#pragma unroll
        for (int n = 0; n < 8; ++n)
#pragma unroll
            for (int e = 0; e < 4; ++e) cs[n][e] = 0.f;
#pragma unroll
        for (int ks = 0; ks < 8; ++ks) {
#pragma unroll
            for (int n = 0; n < 8; ++n) {
                const float* kb = K0 + (n * 8 + g) * FSTR + ks * 8 + t;
                mma_tf32(cs[n], aq[ks][0], aq[ks][1], aq[ks][2], aq[ks][3],
                         __float_as_uint(kb[0]), __float_as_uint(kb[4]));
            }
        }

        if (kt == qt) {
#pragma unroll
            for (int n = 0; n < 8; ++n) {
                int col = n * 8 + 2 * t;
                if (col     > wm + g)     cs[n][0] = -1e30f;
                if (col + 1 > wm + g)     cs[n][1] = -1e30f;
                if (col     > wm + g + 8) cs[n][2] = -1e30f;
                if (col + 1 > wm + g + 8) cs[n][3] = -1e30f;
            }
        }

        // online softmax (two rows per thread)
        float mx0 = -1e30f, mx1 = -1e30f;
#pragma unroll
        for (int n = 0; n < 8; ++n) {
            mx0 = fmaxf(mx0, fmaxf(cs[n][0], cs[n][1]));
            mx1 = fmaxf(mx1, fmaxf(cs[n][2], cs[n][3]));
        }
        mx0 = fmaxf(mx0, __shfl_xor_sync(0xffffffffu, mx0, 1));
        mx0 = fmaxf(mx0, __shfl_xor_sync(0xffffffffu, mx0, 2));
        mx1 = fmaxf(mx1, __shfl_xor_sync(0xffffffffu, mx1, 1));
        mx1 = fmaxf(mx1, __shfl_xor_sync(0xffffffffu, mx1, 2));
        float mn0 = fmaxf(m0, mx0), mn1 = fmaxf(m1, mx1);
        float a0 = exp2f(m0 - mn0), a1 = exp2f(m1 - mn1);

        float s0 = 0.f, s1 = 0.f;
#pragma unroll
        for (int n = 0; n < 8; ++n) {
            float p00 = exp2f(cs[n][0] - mn0);
            float p01 = exp2f(cs[n][1] - mn0);
            float p10 = exp2f(cs[n][2] - mn1);
            float p11 = exp2f(cs[n][3] - mn1);
            s0 += p00 + p01;
            s1 += p10 + p11;
            *(float2*)&sP[(wm + g) * FSTR + n * 8 + 2 * t] =
                make_float2(__uint_as_float(f2tf32(p00)), __uint_as_float(f2tf32(p01)));
            *(float2*)&sP[(wm + g + 8) * FSTR + n * 8 + 2 * t] =
                make_float2(__uint_as_float(f2tf32(p10)), __uint_as_float(f2tf32(p11)));
        }
        s0 += __shfl_xor_sync(0xffffffffu, s0, 1);
        s0 += __shfl_xor_sync(0xffffffffu, s0, 2);
        s1 += __shfl_xor_sync(0xffffffffu, s1, 1);
        s1 += __shfl_xor_sync(0xffffffffu, s1, 2);
        l0 = l0 * a0 + s0;
        l1 = l1 * a1 + s1;
        m0 = mn0; m1 = mn1;
#pragma unroll
        for (int n = 0; n < 8; ++n) {
            o[n][0] *= a0; o[n][1] *= a0;
            o[n][2] *= a1; o[n][3] *= a1;
        }
        __syncwarp();

        // O += P @ V
#pragma unroll
        for (int ks = 0; ks < 8; ++ks) {
            const float* pp = sP + (wm + g) * FSTR + ks * 8 + t;
            uint32_t ap0 = __float_as_uint(pp[0]);
            uint32_t ap1 = __float_as_uint(pp[8 * FSTR]);
            uint32_t ap2 = __float_as_uint(pp[4]);
            uint32_t ap3 = __float_as_uint(pp[8 * FSTR + 4]);
#pragma unroll
            for (int n = 0; n < 8; ++n) {
                const float* vb = V0 + (ks * 8 + t) * FSTR + n * 8 + g;
                mma_tf32(o[n], ap0, ap1, ap2, ap3,
                         __float_as_uint(vb[0]), __float_as_uint(vb[4 * FSTR]));
            }
        }
        __syncthreads();
        if (kt + 2 <= qt) kv_issue(sbase, cur, Kp, Vp, kt + 2, tid);
    }

    float i0 = 1.f / l0, i1 = 1.f / l1;
    float* d0 = attnout + ((size_t)(b * SEQL) + qt * 64 + wm + g) * D_MODEL + h * HD;
#pragma unroll
    for (int n = 0; n < 8; ++n) {
        int col = n * 8 + 2 * t;
        *(float2*)(d0 + col) = make_float2(
            __uint_as_float(f2tf32(o[n][0] * i0)),
            __uint_as_float(f2tf32(o[n][1] * i0)));
        *(float2*)(d0 + 8 * D_MODEL + col) = make_float2(
            __uint_as_float(f2tf32(o[n][2] * i1)),
            __uint_as_float(f2tf32(o[n][3] * i1)));
    }
}

// ---------------------------------------------------------------------------
extern "C" void kernel_launch(void* const* d_in, const int* in_sizes, int n_in,
                              void* d_out, int out_size)
{
    const float* x  = (const float*)d_in[0];
    const int*   tp = (const int*)d_in[1];
    const float* Wq = (const float*)d_in[2];
    const float* Wk = (const float*)d_in[3];
    const float* Wv = (const float*)d_in[4];
    const float* Wo = (const float*)d_in[5];
    float* out = (float*)d_out;

    float *qp, *kp, *vp, *ap, *xcp, *wcp;
    cudaGetSymbolAddress((void**)&qp, g_q);
    cudaGetSymbolAddress((void**)&kp, g_k);
    cudaGetSymbolAddress((void**)&vp, g_v);
    cudaGetSymbolAddress((void**)&ap, g_attn);
    cudaGetSymbolAddress((void**)&xcp, g_xc);
    cudaGetSymbolAddress((void**)&wcp, g_wc);

    static int inited = 0;
    if (!inited) {
        cudaFuncSetAttribute(gemm_tf32, cudaFuncAttributeMaxDynamicSharedMemorySize,
                             GEMM_SMEM);
        cudaFuncSetAttribute(flash_mma, cudaFuncAttributeMaxDynamicSharedMemorySize,
                             FLASH_SMEM);
        inited = 1;
    }

    const float* wc0 = wcp;
    const float* wc1 = wcp + (size_t)D_MODEL * D_MODEL;
    const float* wc2 = wcp + 2 * (size_t)D_MODEL * D_MODEL;
    const float* wc3 = wcp + 3 * (size_t)D_MODEL * D_MODEL;

    // tf32 pre-convert: x and the four weights
    cvt1_kernel<<<(MTOT * D_MODEL / 4 + 255) / 256, 256>>>((const float4*)x,
                                                           (float4*)xcp,
                                                           MTOT * D_MODEL / 4);
    cvt4_kernel<<<dim3(D_MODEL * D_MODEL / 4 / 256, 4), 256>>>(
        (const float4*)Wq, (const float4*)Wk, (const float4*)Wv, (const float4*)Wo);

    // fused QKV projection (+RoPE, +Q scale, tf32 outputs)
    gemm_tf32<<<dim3(D_MODEL / 128, MTOT / 128, 3), 256, GEMM_SMEM>>>(
        xcp, wc0, wc1, wc2, qp, kp, vp, 1, 3, 2, tp);

    flash_mma<<<dim3(SEQL / 64, BSZ * NH), 128, FLASH_SMEM>>>(ap);

    // output projection (fp32 result)
    gemm_tf32<<<dim3(D_MODEL / 128, MTOT / 128, 1), 256, GEMM_SMEM>>>(
        ap, wc3, wc3, wc3, out, out, out, 0, 0, 0, tp);
}